// round 16
// baseline (speedup 1.0000x reference)
#include <cuda_runtime.h>
#include <cuda_fp16.h>

#define N_NODES   200000
#define N_EDGES   3200000
#define HIDDEN    64
#define N_GRAPHS  4096
#define N_CLASSES 7

#define SCAN_BLK  1024
#define N_SBLK    ((N_NODES + SCAN_BLK - 1) / SCAN_BLK)   // 196

// ---------------- scratch (static device globals; no runtime allocation) ----
__device__ __align__(16) __half g_Ah[(size_t)N_NODES * HIDDEN]; // fp16 features
__device__ __align__(16) float  g_B[(size_t)N_NODES * HIDDEN];  // fp32 aggregated
__device__ float g_dinv[N_NODES];
__device__ int   g_count[N_NODES];
__device__ int   g_row[N_NODES + 1];
__device__ int   g_cursor[N_NODES];
__device__ int   g_bsum[N_SBLK];
__device__ __align__(8) int2 g_epack[N_EDGES];   // (src, weight bits) by dst
__device__ float g_sums[N_GRAPHS * HIDDEN];
__device__ float g_cnt[N_GRAPHS];

__device__ __forceinline__ unsigned smem_u32(const void* p) {
    unsigned a;
    asm("{ .reg .u64 t; cvta.to.shared.u64 t, %1; cvt.u32.u64 %0, t; }"
        : "=r"(a) : "l"(p));
    return a;
}

// ---------------- init ------------------------------------------------------
__global__ void k_init() {
    int i = blockIdx.x * blockDim.x + threadIdx.x;
    if (i < N_NODES) g_count[i] = 0;
    if (i < N_GRAPHS * HIDDEN) g_sums[i] = 0.0f;
    if (i < N_GRAPHS) g_cnt[i] = 0.0f;
}

// ---------------- degree histogram over dst ---------------------------------
__global__ void k_deg(const int* __restrict__ dst) {
    int e = blockIdx.x * blockDim.x + threadIdx.x;
    if (e < N_EDGES) atomicAdd(&g_count[dst[e]], 1);
}

// ---------------- prefix scan (3 kernels) -----------------------------------
__global__ void k_scan1() {
    __shared__ int sh[SCAN_BLK];
    int t = threadIdx.x;
    int i = blockIdx.x * SCAN_BLK + t;
    int v = (i < N_NODES) ? g_count[i] : 0;
    sh[t] = v;
    __syncthreads();
    for (int off = 1; off < SCAN_BLK; off <<= 1) {
        int x = (t >= off) ? sh[t - off] : 0;
        __syncthreads();
        sh[t] += x;
        __syncthreads();
    }
    if (i < N_NODES) g_row[i] = sh[t] - v;
    if (t == SCAN_BLK - 1) g_bsum[blockIdx.x] = sh[t];
}

__global__ void k_scan2() {
    __shared__ int sh[256];
    int t = threadIdx.x;
    int v = (t < N_SBLK) ? g_bsum[t] : 0;
    sh[t] = v;
    __syncthreads();
    for (int off = 1; off < 256; off <<= 1) {
        int x = (t >= off) ? sh[t - off] : 0;
        __syncthreads();
        sh[t] += x;
        __syncthreads();
    }
    if (t < N_SBLK) g_bsum[t] = sh[t] - v;
}

__global__ void k_scan3() {
    int i = blockIdx.x * blockDim.x + threadIdx.x;
    if (i >= N_NODES) return;
    int r = g_row[i] + g_bsum[i / SCAN_BLK];
    g_row[i] = r;
    g_cursor[i] = r;
    g_dinv[i] = rsqrtf((float)(g_count[i] + 1));    // +1 self-loop
    if (i == 0) g_row[N_NODES] = N_EDGES;
}

// ---------------- fill CSR --------------------------------------------------
__global__ void k_fill(const int* __restrict__ src, const int* __restrict__ dst) {
    int e = blockIdx.x * blockDim.x + threadIdx.x;
    if (e >= N_EDGES) return;
    int s = src[e];
    int d = dst[e];
    float w = g_dinv[s] * g_dinv[d];
    int pos = atomicAdd(&g_cursor[d], 1);
    g_epack[pos] = make_int2(s, __float_as_int(w));
}

// ---------------- layer 1 dense: x[N,2] @ W1[2,64] -> fp16 A (8 outs/thr) ---
__global__ void k_dense1(const float* __restrict__ x, const float* __restrict__ W1) {
    int idx = blockIdx.x * blockDim.x + threadIdx.x;      // N*8 threads
    if (idx >= N_NODES * 8) return;
    int i = idx >> 3;
    int c = idx & 7;                                      // 8-feature group
    float x0 = x[2 * i], x1 = x[2 * i + 1];
    float4 wa0 = *reinterpret_cast<const float4*>(W1 + 8 * c);
    float4 wa1 = *reinterpret_cast<const float4*>(W1 + 8 * c + 4);
    float4 wb0 = *reinterpret_cast<const float4*>(W1 + 64 + 8 * c);
    float4 wb1 = *reinterpret_cast<const float4*>(W1 + 64 + 8 * c + 4);
    __half2 h0 = __floats2half2_rn(x0 * wa0.x + x1 * wb0.x, x0 * wa0.y + x1 * wb0.y);
    __half2 h1 = __floats2half2_rn(x0 * wa0.z + x1 * wb0.z, x0 * wa0.w + x1 * wb0.w);
    __half2 h2 = __floats2half2_rn(x0 * wa1.x + x1 * wb1.x, x0 * wa1.y + x1 * wb1.y);
    __half2 h3 = __floats2half2_rn(x0 * wa1.z + x1 * wb1.z, x0 * wa1.w + x1 * wb1.w);
    uint4 pk;
    pk.x = *reinterpret_cast<unsigned*>(&h0);
    pk.y = *reinterpret_cast<unsigned*>(&h1);
    pk.z = *reinterpret_cast<unsigned*>(&h2);
    pk.w = *reinterpret_cast<unsigned*>(&h3);
    reinterpret_cast<uint4*>(g_Ah)[idx] = pk;
}

// ---------------- layers 2/3 dense via tensor cores -------------------------
// relu(B + b_prev) @ W[64,64] -> fp16 A.  Block: 128 thr = 4 warps = 64 nodes,
// each warp computes a 16x64 output tile with mma.sync.m16n8k16 (f16 in, f32 acc).
#define DPAD 72   // smem row stride in halves (8-half pad kills ldmatrix conflicts)
__global__ void k_dense(const float* __restrict__ W, const float* __restrict__ bprev) {
    __shared__ __half Wh[64 * DPAD];
    __shared__ __half Ih[64 * DPAD];
    int t = threadIdx.x;
    int lane = t & 31;
    int warp = t >> 5;
    int nodeBase = blockIdx.x * 64;

    // W[64x64] fp32 -> fp16 smem (row-major k x n)
    for (int i = t; i < 4096; i += 128)
        Wh[(i >> 6) * DPAD + (i & 63)] = __float2half_rn(W[i]);

    // inputs: relu(B + bias) -> fp16 smem (row = local node)
    for (int i = t; i < 1024; i += 128) {                 // 1024 float4s
        int node = i >> 4;
        int jj = i & 15;
        float4 v = reinterpret_cast<const float4*>(g_B)[(nodeBase + node) * 16 + jj];
        float4 bb = reinterpret_cast<const float4*>(bprev)[jj];
        __half2 p0 = __floats2half2_rn(fmaxf(v.x + bb.x, 0.0f), fmaxf(v.y + bb.y, 0.0f));
        __half2 p1 = __floats2half2_rn(fmaxf(v.z + bb.z, 0.0f), fmaxf(v.w + bb.w, 0.0f));
        __half2* dstp = reinterpret_cast<__half2*>(&Ih[node * DPAD + jj * 4]);
        dstp[0] = p0;
        dstp[1] = p1;
    }
    __syncthreads();

    // A fragments: 4 k-tiles of 16x16 from Ih
    unsigned baseI = smem_u32(Ih);
    unsigned baseW = smem_u32(Wh);
    int warpM = warp * 16;
    unsigned a[4][4];
#pragma unroll
    for (int kt = 0; kt < 4; kt++) {
        unsigned addr = baseI + (((warpM + (lane & 15)) * DPAD) + kt * 16 + ((lane >> 4) << 3)) * 2;
        asm volatile("ldmatrix.sync.aligned.m8n8.x4.shared.b16 {%0,%1,%2,%3}, [%4];"
                     : "=r"(a[kt][0]), "=r"(a[kt][1]), "=r"(a[kt][2]), "=r"(a[kt][3])
                     : "r"(addr));
    }

    int r0 = lane >> 2;                 // output row within tile
    int cc = (lane & 3) * 2;            // output col pair within n-tile
#pragma unroll
    for (int nt = 0; nt < 8; nt++) {
        float c0 = 0.f, c1 = 0.f, c2 = 0.f, c3 = 0.f;
#pragma unroll
        for (int kt = 0; kt < 4; kt++) {
            unsigned b0, b1;
            unsigned addr = baseW + ((kt * 16 + (lane & 15)) * DPAD + nt * 8) * 2;
            asm volatile("ldmatrix.sync.aligned.m8n8.x2.trans.shared.b16 {%0,%1}, [%2];"
                         : "=r"(b0), "=r"(b1) : "r"(addr));
            asm volatile(
                "mma.sync.aligned.m16n8k16.row.col.f32.f16.f16.f32 "
                "{%0,%1,%2,%3}, {%4,%5,%6,%7}, {%8,%9}, {%0,%1,%2,%3};"
                : "+f"(c0), "+f"(c1), "+f"(c2), "+f"(c3)
                : "r"(a[kt][0]), "r"(a[kt][1]), "r"(a[kt][2]), "r"(a[kt][3]),
                  "r"(b0), "r"(b1));
        }
        int col = nt * 8 + cc;
        __half2 h01 = __floats2half2_rn(c0, c1);
        __half2 h23 = __floats2half2_rn(c2, c3);
        *reinterpret_cast<__half2*>(&g_Ah[(size_t)(nodeBase + warpM + r0) * 64 + col]) = h01;
        *reinterpret_cast<__half2*>(&g_Ah[(size_t)(nodeBase + warpM + r0 + 8) * 64 + col]) = h23;
    }
}

// ---------------- pull aggregation ------------------------------------------
// 8 lanes per node, each owns 16B (8 halves) of the 128B fp16 row -> LDG.128
// gathers. fp32 accumulate, no atomics, B written once.
__device__ __forceinline__ void agg_edge(float acc[8], uint4 q, float w) {
    float2 u0 = __half22float2(*reinterpret_cast<const __half2*>(&q.x));
    float2 u1 = __half22float2(*reinterpret_cast<const __half2*>(&q.y));
    float2 u2 = __half22float2(*reinterpret_cast<const __half2*>(&q.z));
    float2 u3 = __half22float2(*reinterpret_cast<const __half2*>(&q.w));
    acc[0] += w * u0.x; acc[1] += w * u0.y;
    acc[2] += w * u1.x; acc[3] += w * u1.y;
    acc[4] += w * u2.x; acc[5] += w * u2.y;
    acc[6] += w * u3.x; acc[7] += w * u3.y;
}

__global__ void k_agg() {
    int t = threadIdx.x;
    int node = blockIdx.x * 32 + (t >> 3);          // 32 nodes / 256-thr block
    int c = t & 7;                                  // 8 lanes per node
    const uint4* __restrict__ a16 = reinterpret_cast<const uint4*>(g_Ah);
    float di = g_dinv[node];
    float ws = di * di;
    float acc[8];
    {
        uint4 sp = a16[node * 8 + c];
        float2 u0 = __half22float2(*reinterpret_cast<const __half2*>(&sp.x));
        float2 u1 = __half22float2(*reinterpret_cast<const __half2*>(&sp.y));
        float2 u2 = __half22float2(*reinterpret_cast<const __half2*>(&sp.z));
        float2 u3 = __half22float2(*reinterpret_cast<const __half2*>(&sp.w));
        acc[0] = ws * u0.x; acc[1] = ws * u0.y;
        acc[2] = ws * u1.x; acc[3] = ws * u1.y;
        acc[4] = ws * u2.x; acc[5] = ws * u2.y;
        acc[6] = ws * u3.x; acc[7] = ws * u3.y;
    }
    int b = g_row[node];
    int e = g_row[node + 1];
    int i = b;
    for (; i + 3 < e; i += 4) {
        int2 p0 = g_epack[i],     p1 = g_epack[i + 1];
        int2 p2 = g_epack[i + 2], p3 = g_epack[i + 3];
        uint4 q0 = a16[p0.x * 8 + c];
        uint4 q1 = a16[p1.x * 8 + c];
        uint4 q2 = a16[p2.x * 8 + c];
        uint4 q3 = a16[p3.x * 8 + c];
        agg_edge(acc, q0, __int_as_float(p0.y));
        agg_edge(acc, q1, __int_as_float(p1.y));
        agg_edge(acc, q2, __int_as_float(p2.y));
        agg_edge(acc, q3, __int_as_float(p3.y));
    }
    for (; i < e; i++) {
        int2 p = g_epack[i];
        uint4 q = a16[p.x * 8 + c];
        agg_edge(acc, q, __int_as_float(p.y));
    }
    float4* B4 = reinterpret_cast<float4*>(g_B);
    B4[node * 16 + c * 2 + 0] = make_float4(acc[0], acc[1], acc[2], acc[3]);
    B4[node * 16 + c * 2 + 1] = make_float4(acc[4], acc[5], acc[6], acc[7]);
}

// ---------------- pool: run-length compressed atomics (batch sorted) --------
__global__ void k_pool(const int* __restrict__ batch, const float* __restrict__ b3) {
    int t = threadIdx.x;
    int j = t & 63;
    int base = (blockIdx.x * 4 + (t >> 6)) * 16;
    float bias = b3[j];
    int gcur = batch[base];
    float acc = 0.0f;
    int cnt = 0;
#pragma unroll
    for (int k = 0; k < 16; k++) {
        int node = base + k;
        int g = batch[node];
        if (g != gcur) {
            atomicAdd(&g_sums[gcur * 64 + j], acc);
            if (j == 0) atomicAdd(&g_cnt[gcur], (float)cnt);
            acc = 0.0f; cnt = 0; gcur = g;
        }
        acc += fmaxf(g_B[node * 64 + j] + bias, 0.0f);
        cnt++;
    }
    atomicAdd(&g_sums[gcur * 64 + j], acc);
    if (j == 0) atomicAdd(&g_cnt[gcur], (float)cnt);
}

// ---------------- MLP head --------------------------------------------------
__global__ void k_mlp(const float* __restrict__ Wf1, const float* __restrict__ bf1,
                      const float* __restrict__ Wf2, const float* __restrict__ bf2,
                      float* __restrict__ out) {
    __shared__ float p[64];
    __shared__ float hid[64];
    int g = blockIdx.x;
    int tx = threadIdx.x;
    float cnt = fmaxf(g_cnt[g], 1.0f);
    p[tx] = g_sums[g * 64 + tx] / cnt;
    __syncthreads();
    float a = bf1[tx];
#pragma unroll
    for (int k = 0; k < 64; k++) a += p[k] * Wf1[k * 64 + tx];
    hid[tx] = fmaxf(a, 0.0f);
    __syncthreads();
    if (tx < N_CLASSES) {
        float o = bf2[tx];
#pragma unroll
        for (int k = 0; k < 64; k++) o += hid[k] * Wf2[k * N_CLASSES + tx];
        out[g * N_CLASSES + tx] = o;
    }
}

// ---------------- launch ----------------------------------------------------
extern "C" void kernel_launch(void* const* d_in, const int* in_sizes, int n_in,
                              void* d_out, int out_size) {
    const float* x     = (const float*)d_in[0];
    const int*   ei    = (const int*)d_in[1];     // [2, E] int32
    const int*   batch = (const int*)d_in[2];     // [N] int32
    const float* W1  = (const float*)d_in[3];
    const float* b1  = (const float*)d_in[4];
    const float* W2  = (const float*)d_in[5];
    const float* b2  = (const float*)d_in[6];
    const float* W3  = (const float*)d_in[7];
    const float* b3  = (const float*)d_in[8];
    const float* Wf1 = (const float*)d_in[9];
    const float* bf1 = (const float*)d_in[10];
    const float* Wf2 = (const float*)d_in[11];
    const float* bf2 = (const float*)d_in[12];
    float* out = (float*)d_out;

    const int* src = ei;
    const int* dst = ei + N_EDGES;

    const int gridEdge = (N_EDGES + 255) / 256;     // 12500
    const int gridNode = (N_NODES + 255) / 256;     // 782
    const int gridAgg  = N_NODES / 32;              // 6250
    const int gridDense = N_NODES / 64;             // 3125

    // ---- CSR build (once, reused by all 3 layers) ----
    k_init<<<(N_GRAPHS * HIDDEN + 255) / 256, 256>>>();
    k_deg<<<gridEdge, 256>>>(dst);
    k_scan1<<<N_SBLK, SCAN_BLK>>>();
    k_scan2<<<1, 256>>>();
    k_scan3<<<gridNode, 256>>>();
    k_fill<<<gridEdge, 256>>>(src, dst);

    // ---- layer 1 ----
    k_dense1<<<(N_NODES * 8 + 255) / 256, 256>>>(x, W1);
    k_agg<<<gridAgg, 256>>>();
    // ---- layer 2 (applies b1+relu) ----
    k_dense<<<gridDense, 128>>>(W2, b1);
    k_agg<<<gridAgg, 256>>>();
    // ---- layer 3 (applies b2+relu) ----
    k_dense<<<gridDense, 128>>>(W3, b2);
    k_agg<<<gridAgg, 256>>>();

    // ---- pool (applies b3+relu) + head ----
    k_pool<<<N_NODES / 64, 256>>>(batch, b3);
    k_mlp<<<N_GRAPHS, 64>>>(Wf1, bf1, Wf2, bf2, out);
}